// round 8
// baseline (speedup 1.0000x reference)
#include <cuda_runtime.h>
#include <cuda_bf16.h>
#include <cuda_fp16.h>
#include <stdint.h>
#include <math.h>

#define SEQ 4096
#define HID 1280
#define NH 16
#define HD 80
#define HALF 40

// ---------------- scratch (device globals) ----------------------------------
__device__ float g_qkv[(size_t)SEQ * 3 * HID];

// fp16 operands for dense GEMMs
__device__ __half g_h16[(size_t)SEQ * HID];          // hidden, fp16
__device__ __half g_wh16[(size_t)3 * HID * HID];     // qkv_w hi
__device__ __half g_wl16[(size_t)3 * HID * HID];     // qkv_w lo
__device__ __half g_ph16[(size_t)HID * HID];         // proj_w hi
__device__ __half g_pl16[(size_t)HID * HID];         // proj_w lo
__device__ __half g_o16[(size_t)SEQ * HID];          // attention out, fp16

// split Q/K/V (bf16 hi/lo), head-major; Q pre-scaled by HD^-0.5
__device__ __nv_bfloat16 g_qh[(size_t)NH * SEQ * HD];
__device__ __nv_bfloat16 g_ql[(size_t)NH * SEQ * HD];
__device__ __nv_bfloat16 g_kh[(size_t)NH * SEQ * HD];
__device__ __nv_bfloat16 g_kl[(size_t)NH * SEQ * HD];
__device__ __nv_bfloat16 g_vh[(size_t)NH * SEQ * HD];
__device__ __nv_bfloat16 g_vl[(size_t)NH * SEQ * HD];

// ---------------- PTX helpers ----------------------------------------------
__device__ __forceinline__ uint32_t smem_u32(const void* p) {
    uint32_t a;
    asm("{ .reg .u64 t; cvta.to.shared.u64 t, %1; cvt.u32.u64 %0, t; }"
        : "=r"(a) : "l"(p));
    return a;
}

__device__ __forceinline__ void ldsm4(uint32_t* r, uint32_t addr) {
    asm volatile("ldmatrix.sync.aligned.m8n8.x4.shared.b16 {%0,%1,%2,%3}, [%4];\n"
        : "=r"(r[0]), "=r"(r[1]), "=r"(r[2]), "=r"(r[3]) : "r"(addr));
}

__device__ __forceinline__ void ldsm4t(uint32_t* r, uint32_t addr) {
    asm volatile("ldmatrix.sync.aligned.m8n8.x4.trans.shared.b16 {%0,%1,%2,%3}, [%4];\n"
        : "=r"(r[0]), "=r"(r[1]), "=r"(r[2]), "=r"(r[3]) : "r"(addr));
}

// bf16 MMA (attention)
__device__ __forceinline__ void mma16816(float* d, const uint32_t* a,
                                         const uint32_t* b) {
    asm volatile(
        "mma.sync.aligned.m16n8k16.row.col.f32.bf16.bf16.f32 "
        "{%0,%1,%2,%3}, {%4,%5,%6,%7}, {%8,%9}, {%0,%1,%2,%3};\n"
        : "+f"(d[0]), "+f"(d[1]), "+f"(d[2]), "+f"(d[3])
        : "r"(a[0]), "r"(a[1]), "r"(a[2]), "r"(a[3]), "r"(b[0]), "r"(b[1]));
}

// fp16 MMA (dense GEMMs)
__device__ __forceinline__ void mma16816h(float* d, const uint32_t* a,
                                          const uint32_t* b) {
    asm volatile(
        "mma.sync.aligned.m16n8k16.row.col.f32.f16.f16.f32 "
        "{%0,%1,%2,%3}, {%4,%5,%6,%7}, {%8,%9}, {%0,%1,%2,%3};\n"
        : "+f"(d[0]), "+f"(d[1]), "+f"(d[2]), "+f"(d[3])
        : "r"(a[0]), "r"(a[1]), "r"(a[2]), "r"(a[3]), "r"(b[0]), "r"(b[1]));
}

__device__ __forceinline__ void cp16(uint32_t s, const void* g) {
    asm volatile("cp.async.cg.shared.global [%0], [%1], 16;\n" :: "r"(s), "l"(g));
}

__device__ __forceinline__ void splitpack(float x0, float x1,
                                          uint32_t& ph, uint32_t& pl) {
    __nv_bfloat162 h = __floats2bfloat162_rn(x0, x1);
    float h0 = __bfloat162float(h.x), h1 = __bfloat162float(h.y);
    __nv_bfloat162 l = __floats2bfloat162_rn(x0 - h0, x1 - h1);
    ph = *(uint32_t*)&h;
    pl = *(uint32_t*)&l;
}

// ---------------- conversion kernels ----------------------------------------
__global__ __launch_bounds__(256) void cvt16_kernel(
    const float* __restrict__ src, __half* __restrict__ dst, int n)
{
    int i = blockIdx.x * blockDim.x + threadIdx.x;
    if (i < n) dst[i] = __float2half_rn(src[i]);
}

__global__ __launch_bounds__(256) void split16_kernel(
    const float* __restrict__ src, __half* __restrict__ hi,
    __half* __restrict__ lo, int n)
{
    int i = blockIdx.x * blockDim.x + threadIdx.x;
    if (i >= n) return;
    float x = src[i];
    __half h = __float2half_rn(x);
    hi[i] = h;
    lo[i] = __float2half_rn(x - __half2float(h));
}

// ---------------- fp16 2-term HMMA GEMM: C = Ah*(Bh+Bl) + bias --------------
// 128x128 CTA, 8 warps (64x32 each), BK=32, double-buffered, 2 CTAs/SM.
#define BK 32
#define ASTR 40                       // fp16 elems per smem row (80B)
#define TILE_B (128 * ASTR * 2)       // 10240 bytes per tile
#define STAGE_B (3 * TILE_B)          // A, Bh, Bl = 30720 bytes
#define HMMA_SMEM (2 * STAGE_B)       // 61440 bytes

__device__ __forceinline__ void gemm_prefetch(
    uint32_t sstage,
    const __half* __restrict__ Ag,
    const __half* __restrict__ Bgh, const __half* __restrict__ Bgl,
    int k0, int K, int tid)
{
    #pragma unroll
    for (int it = 0; it < 2; it++) {
        int idx = tid + it * 256;
        int r = idx >> 2, c8 = (idx & 3) << 3;
        uint32_t soff = (uint32_t)(r * ASTR + c8) * 2;
        size_t ga = (size_t)r * K + k0 + c8;
        cp16(sstage + soff,               Ag + ga);
        cp16(sstage + TILE_B + soff,      Bgh + ga);
        cp16(sstage + 2 * TILE_B + soff,  Bgl + ga);
    }
}

__global__ __launch_bounds__(256, 2) void hmma_gemm_kernel(
    const __half* __restrict__ A,
    const __half* __restrict__ Bh, const __half* __restrict__ Bl,
    const float* __restrict__ bias, float* __restrict__ C, int N, int K)
{
    extern __shared__ char smraw[];
    const uint32_t sb = smem_u32(smraw);
    const int tid = threadIdx.x;
    const int wid = tid >> 5, lane = tid & 31;
    const int wm = (wid >> 2) * 64;
    const int wn = (wid & 3) * 32;
    const int bm = blockIdx.y * 128, bn = blockIdx.x * 128;

    const int lg = lane >> 3, lr = lane & 7;
    const int a_r = lr + ((lg & 1) << 3), a_c = (lg >> 1) << 3;
    const int b_r = lr + ((lg >> 1) << 3), b_c = (lg & 1) << 3;

    const __half* Ag  = A  + (size_t)bm * K;
    const __half* Bgh = Bh + (size_t)bn * K;
    const __half* Bgl = Bl + (size_t)bn * K;

    float acc[4][4][4];
    #pragma unroll
    for (int i = 0; i < 4; i++)
        #pragma unroll
        for (int j = 0; j < 4; j++)
            #pragma unroll
            for (int t = 0; t < 4; t++) acc[i][j][t] = 0.f;

    const int nc = K / BK;
    gemm_prefetch(sb, Ag, Bgh, Bgl, 0, K, tid);
    asm volatile("cp.async.commit_group;\n" ::: "memory");

    for (int c = 0; c < nc; c++) {
        if (c + 1 < nc) {
            gemm_prefetch(sb + ((c + 1) & 1) * STAGE_B, Ag, Bgh, Bgl,
                          (c + 1) * BK, K, tid);
            asm volatile("cp.async.commit_group;\n" ::: "memory");
            asm volatile("cp.async.wait_group 1;\n" ::: "memory");
        } else {
            asm volatile("cp.async.wait_group 0;\n" ::: "memory");
        }
        __syncthreads();

        const uint32_t s0 = sb + (c & 1) * STAGE_B;
        const uint32_t aA = s0;
        const uint32_t bH = s0 + TILE_B, bL = s0 + 2 * TILE_B;

        #pragma unroll
        for (int ks = 0; ks < 2; ks++) {
            const int k = ks * 16;
            uint32_t af[4][4], bhf[2][4], blf[2][4];
            #pragma unroll
            for (int i = 0; i < 4; i++) {
                uint32_t off = (uint32_t)((wm + i * 16 + a_r) * ASTR + k + a_c) * 2;
                ldsm4(af[i], aA + off);
            }
            #pragma unroll
            for (int p = 0; p < 2; p++) {
                uint32_t off = (uint32_t)((wn + p * 16 + b_r) * ASTR + k + b_c) * 2;
                ldsm4(bhf[p], bH + off);
                ldsm4(blf[p], bL + off);
            }
            #pragma unroll
            for (int i = 0; i < 4; i++)
                #pragma unroll
                for (int j = 0; j < 4; j++) {
                    const uint32_t* bhp = &bhf[j >> 1][(j & 1) * 2];
                    const uint32_t* blp = &blf[j >> 1][(j & 1) * 2];
                    mma16816h(acc[i][j], af[i], bhp);
                    mma16816h(acc[i][j], af[i], blp);
                }
        }
        __syncthreads();
    }

    #pragma unroll
    for (int i = 0; i < 4; i++) {
        int r0 = bm + wm + i * 16 + (lane >> 2);
        #pragma unroll
        for (int j = 0; j < 4; j++) {
            int c0 = bn + wn + j * 8 + ((lane & 3) << 1);
            float b0 = __ldg(bias + c0), b1 = __ldg(bias + c0 + 1);
            *(float2*)(C + (size_t)r0 * N + c0) =
                make_float2(acc[i][j][0] + b0, acc[i][j][1] + b1);
            *(float2*)(C + (size_t)(r0 + 8) * N + c0) =
                make_float2(acc[i][j][2] + b0, acc[i][j][3] + b1);
        }
    }
}

// ---------------- RoPE + split to bf16 hi/lo, head-major --------------------
__global__ __launch_bounds__(256) void rope_split_kernel(
    const float* __restrict__ cosp, const float* __restrict__ sinp)
{
    int idx = blockIdx.x * blockDim.x + threadIdx.x;
    if (idx >= SEQ * NH * HD) return;
    int d = idx % HD;
    int h = (idx / HD) % NH;
    int s = idx / (HD * NH);
    float c = cosp[s * HD + d], sn = sinp[s * HD + d];
    const float* base = g_qkv + (size_t)s * 3 * HID + h * HD;
    float qv = base[d];
    float kv = base[HID + d];
    float vv = base[2 * HID + d];
    float qr = (d < HALF) ? -base[d + HALF] : base[d - HALF];
    float kr = (d < HALF) ? -base[HID + d + HALF] : base[HID + d - HALF];
    const float scale = rsqrtf((float)HD);
    float q = (qv * c + qr * sn) * scale;
    float k = kv * c + kr * sn;
    size_t o = (size_t)h * SEQ * HD + (size_t)s * HD + d;
    __nv_bfloat16 qh = __float2bfloat16(q);
    __nv_bfloat16 kh = __float2bfloat16(k);
    __nv_bfloat16 vh = __float2bfloat16(vv);
    g_qh[o] = qh; g_ql[o] = __float2bfloat16(q - __bfloat162float(qh));
    g_kh[o] = kh; g_kl[o] = __float2bfloat16(k - __bfloat162float(kh));
    g_vh[o] = vh; g_vl[o] = __float2bfloat16(vv - __bfloat162float(vh));
}

// ---------------- HMMA flash attention (bf16 3-term, fp32 acc) --------------
#define QSTR 88
#define ATILE (128 * QSTR * 2)
#define ATTN_SMEM (6 * ATILE)

__global__ __launch_bounds__(256, 1) void hmma_attn_kernel(
    const __nv_bfloat16* __restrict__ Qh_, const __nv_bfloat16* __restrict__ Ql_,
    const __nv_bfloat16* __restrict__ Kh_, const __nv_bfloat16* __restrict__ Kl_,
    const __nv_bfloat16* __restrict__ Vh_, const __nv_bfloat16* __restrict__ Vl_,
    const int* __restrict__ cu, int nseg,
    __half* __restrict__ O_)
{
    extern __shared__ char smraw[];
    const uint32_t sb = smem_u32(smraw);
    const uint32_t sQh = sb,             sQl = sb + ATILE;
    const uint32_t sKh = sb + 2 * ATILE, sKl = sb + 3 * ATILE;
    const uint32_t sVh = sb + 4 * ATILE, sVl = sb + 5 * ATILE;
    __shared__ int cus[17];

    const int tid = threadIdx.x;
    const int wid = tid >> 5, lane = tid & 31;
    const int h = blockIdx.y;
    const int r0 = blockIdx.x * 128;

    const int lg = lane >> 3, lr = lane & 7;
    const int a_r = lr + ((lg & 1) << 3), a_c = (lg >> 1) << 3;
    const int b_r = lr + ((lg >> 1) << 3), b_c = (lg & 1) << 3;

    if (tid <= nseg) cus[tid] = cu[tid];

    {
        const __nv_bfloat16* qh = Qh_ + ((size_t)h * SEQ + r0) * HD;
        const __nv_bfloat16* ql = Ql_ + ((size_t)h * SEQ + r0) * HD;
        for (int idx = tid; idx < 128 * 10; idx += 256) {
            int row = idx / 10, c8 = (idx % 10) * 8;
            uint32_t soff = (uint32_t)(row * QSTR + c8) * 2;
            cp16(sQh + soff, qh + (size_t)row * HD + c8);
            cp16(sQl + soff, ql + (size_t)row * HD + c8);
        }
        asm volatile("cp.async.commit_group;\n" ::: "memory");
    }
    __syncthreads();

    const int gr1 = r0 + 16 * wid + (lane >> 2);
    int st1 = 0, en1 = SEQ, st2 = 0, en2 = SEQ;
    for (int t = 0; t < nseg; t++) {
        if (gr1     >= cus[t]) { st1 = cus[t]; en1 = cus[t + 1]; }
        if (gr1 + 8 >= cus[t]) { st2 = cus[t]; en2 = cus[t + 1]; }
    }
    int blk_start = 0, blk_end = SEQ;
    for (int t = 0; t < nseg; t++) {
        if (r0 >= cus[t]) blk_start = cus[t];
        if (r0 + 127 >= cus[t]) blk_end = cus[t + 1];
    }
    const int kb0 = (blk_start / 128) * 128;

    float m1 = -INFINITY, m2 = -INFINITY, l1 = 0.f, l2 = 0.f;
    float oacc[10][4];
    #pragma unroll
    for (int j = 0; j < 10; j++)
        #pragma unroll
        for (int t = 0; t < 4; t++) oacc[j][t] = 0.f;

    const __nv_bfloat16* Kgh = Kh_ + (size_t)h * SEQ * HD;
    const __nv_bfloat16* Kgl = Kl_ + (size_t)h * SEQ * HD;
    const __nv_bfloat16* Vgh = Vh_ + (size_t)h * SEQ * HD;
    const __nv_bfloat16* Vgl = Vl_ + (size_t)h * SEQ * HD;

    for (int kb = kb0; kb < blk_end; kb += 128) {
        __syncthreads();
        for (int idx = tid; idx < 128 * 10; idx += 256) {
            int row = idx / 10, c8 = (idx % 10) * 8;
            uint32_t soff = (uint32_t)(row * QSTR + c8) * 2;
            size_t ga = (size_t)(kb + row) * HD + c8;
            cp16(sKh + soff, Kgh + ga);
            cp16(sKl + soff, Kgl + ga);
            cp16(sVh + soff, Vgh + ga);
            cp16(sVl + soff, Vgl + ga);
        }
        asm volatile("cp.async.commit_group;\n" ::: "memory");
        asm volatile("cp.async.wait_group 0;\n" ::: "memory");
        __syncthreads();

        float sc[16][4];
        #pragma unroll
        for (int j = 0; j < 16; j++)
            #pragma unroll
            for (int t = 0; t < 4; t++) sc[j][t] = 0.f;

        #pragma unroll
        for (int kc = 0; kc < 5; kc++) {
            uint32_t ah[4], al[4];
            uint32_t qoff = (uint32_t)((16 * wid + a_r) * QSTR + kc * 16 + a_c) * 2;
            ldsm4(ah, sQh + qoff);
            ldsm4(al, sQl + qoff);
            #pragma unroll
            for (int ng = 0; ng < 8; ng++) {
                uint32_t bh[4], bl[4];
                uint32_t koff = (uint32_t)((ng * 16 + b_r) * QSTR + kc * 16 + b_c) * 2;
                ldsm4(bh, sKh + koff);
                ldsm4(bl, sKl + koff);
                mma16816(sc[2 * ng],     ah, bh);
                mma16816(sc[2 * ng],     ah, bl);
                mma16816(sc[2 * ng],     al, bh);
                mma16816(sc[2 * ng + 1], ah, bh + 2);
                mma16816(sc[2 * ng + 1], ah, bl + 2);
                mma16816(sc[2 * ng + 1], al, bh + 2);
            }
        }

        float tm1 = -INFINITY, tm2 = -INFINITY;
        #pragma unroll
        for (int j = 0; j < 16; j++) {
            int c0 = kb + j * 8 + ((lane & 3) << 1);
            int c1 = c0 + 1;
            if (c0 < st1 || c0 >= en1) sc[j][0] = -INFINITY;
            if (c1 < st1 || c1 >= en1) sc[j][1] = -INFINITY;
            if (c0 < st2 || c0 >= en2) sc[j][2] = -INFINITY;
            if (c1 < st2 || c1 >= en2) sc[j][3] = -INFINITY;
            tm1 = fmaxf(tm1, fmaxf(sc[j][0], sc[j][1]));
            tm2 = fmaxf(tm2, fmaxf(sc[j][2], sc[j][3]));
        }
        tm1 = fmaxf(tm1, __shfl_xor_sync(0xffffffffu, tm1, 1, 4));
        tm1 = fmaxf(tm1, __shfl_xor_sync(0xffffffffu, tm1, 2, 4));
        tm2 = fmaxf(tm2, __shfl_xor_sync(0xffffffffu, tm2, 1, 4));
        tm2 = fmaxf(tm2, __shfl_xor_sync(0xffffffffu, tm2, 2, 4));

        float mn1 = fmaxf(m1, tm1), mn2 = fmaxf(m2, tm2);
        bool dead1 = (mn1 == -INFINITY), dead2 = (mn2 == -INFINITY);
        float f1 = dead1 ? 1.f : __expf(m1 - mn1);
        float f2 = dead2 ? 1.f : __expf(m2 - mn2);
        m1 = mn1; m2 = mn2;

        float rs1 = 0.f, rs2 = 0.f;
        #pragma unroll
        for (int j = 0; j < 16; j++) {
            float p0 = dead1 ? 0.f : __expf(sc[j][0] - mn1);
            float p1 = dead1 ? 0.f : __expf(sc[j][1] - mn1);
            float p2 = dead2 ? 0.f : __expf(sc[j][2] - mn2);
            float p3 = dead2 ? 0.f : __expf(sc[j][3] - mn2);
            sc[j][0] = p0; sc[j][1] = p1; sc[j][2] = p2; sc[j][3] = p3;
            rs1 += p0 + p1; rs2 += p2 + p3;
        }
        rs1 += __shfl_xor_sync(0xffffffffu, rs1, 1, 4);
        rs1 += __shfl_xor_sync(0xffffffffu, rs1, 2, 4);
        rs2 += __shfl_xor_sync(0xffffffffu, rs2, 1, 4);
        rs2 += __shfl_xor_sync(0xffffffffu, rs2, 2, 4);
        l1 = l1 * f1 + rs1;
        l2 = l2 * f2 + rs2;

        #pragma unroll
        for (int j = 0; j < 10; j++) {
            oacc[j][0] *= f1; oacc[j][1] *= f1;
            oacc[j][2] *= f2; oacc[j][3] *= f2;
        }

        #pragma unroll
        for (int kc = 0; kc < 8; kc++) {
            uint32_t pah[4], pal[4];
            splitpack(sc[2 * kc][0],     sc[2 * kc][1],     pah[0], pal[0]);
            splitpack(sc[2 * kc][2],     sc[2 * kc][3],     pah[1], pal[1]);
            splitpack(sc[2 * kc + 1][0], sc[2 * kc + 1][1], pah[2], pal[2]);
            splitpack(sc[2 * kc + 1][2], sc[2 * kc + 1][3], pah[3], pal[3]);
            #pragma unroll
            for (int dv = 0; dv < 5; dv++) {
                uint32_t vh[4], vl[4];
                uint32_t voff = (uint32_t)((kc * 16 + (lane & 15)) * QSTR
                                 + dv * 16 + ((lane >> 4) << 3)) * 2;
                ldsm4t(vh, sVh + voff);
                ldsm4t(vl, sVl + voff);
                mma16816(oacc[2 * dv],     pah, vh);
                mma16816(oacc[2 * dv],     pah, vl);
                mma16816(oacc[2 * dv],     pal, vh);
                mma16816(oacc[2 * dv + 1], pah, vh + 2);
                mma16816(oacc[2 * dv + 1], pah, vl + 2);
                mma16816(oacc[2 * dv + 1], pal, vh + 2);
            }
        }
    }

    float inv1 = (l1 > 0.f) ? 1.f / l1 : 0.f;
    float inv2 = (l2 > 0.f) ? 1.f / l2 : 0.f;
    #pragma unroll
    for (int j = 0; j < 10; j++) {
        int dcol = h * HD + j * 8 + ((lane & 3) << 1);
        __half2 h2a = __floats2half2_rn(oacc[j][0] * inv1, oacc[j][1] * inv1);
        __half2 h2b = __floats2half2_rn(oacc[j][2] * inv2, oacc[j][3] * inv2);
        *(__half2*)(O_ + (size_t)gr1 * HID + dcol) = h2a;
        *(__half2*)(O_ + (size_t)(gr1 + 8) * HID + dcol) = h2b;
    }
}

// ---------------- launch ----------------------------------------------------
extern "C" void kernel_launch(void* const* d_in, const int* in_sizes, int n_in,
                              void* d_out, int out_size)
{
    const float* hidden = (const float*)d_in[0];
    const float* cosp   = (const float*)d_in[1];
    const float* sinp   = (const float*)d_in[2];
    const float* qkv_w  = (const float*)d_in[3];
    const float* qkv_b  = (const float*)d_in[4];
    const float* proj_w = (const float*)d_in[5];
    const float* proj_b = (const float*)d_in[6];
    const int*   cu     = (const int*)d_in[7];
    const int    nseg   = in_sizes[7] - 1;
    float* out = (float*)d_out;

    float* qkv;
    cudaGetSymbolAddress((void**)&qkv, g_qkv);
    __half *h16, *wh16, *wl16, *ph16, *pl16, *o16;
    cudaGetSymbolAddress((void**)&h16,  g_h16);
    cudaGetSymbolAddress((void**)&wh16, g_wh16);
    cudaGetSymbolAddress((void**)&wl16, g_wl16);
    cudaGetSymbolAddress((void**)&ph16, g_ph16);
    cudaGetSymbolAddress((void**)&pl16, g_pl16);
    cudaGetSymbolAddress((void**)&o16,  g_o16);
    __nv_bfloat16 *qh, *ql, *kh, *kl, *vh, *vl;
    cudaGetSymbolAddress((void**)&qh, g_qh);
    cudaGetSymbolAddress((void**)&ql, g_ql);
    cudaGetSymbolAddress((void**)&kh, g_kh);
    cudaGetSymbolAddress((void**)&kl, g_kl);
    cudaGetSymbolAddress((void**)&vh, g_vh);
    cudaGetSymbolAddress((void**)&vl, g_vl);

    cudaFuncSetAttribute(hmma_gemm_kernel,
                         cudaFuncAttributeMaxDynamicSharedMemorySize, HMMA_SMEM);
    cudaFuncSetAttribute(hmma_attn_kernel,
                         cudaFuncAttributeMaxDynamicSharedMemorySize, ATTN_SMEM);

    // 0) conversions
    {
        int n1 = SEQ * HID;
        cvt16_kernel<<<(n1 + 255) / 256, 256>>>(hidden, h16, n1);
        int n2 = 3 * HID * HID;
        split16_kernel<<<(n2 + 255) / 256, 256>>>(qkv_w, wh16, wl16, n2);
        int n3 = HID * HID;
        split16_kernel<<<(n3 + 255) / 256, 256>>>(proj_w, ph16, pl16, n3);
    }
    // 1) QKV GEMM (fp16 2-term HMMA)
    {
        dim3 grid((3 * HID) / 128, SEQ / 128);
        hmma_gemm_kernel<<<grid, 256, HMMA_SMEM>>>(h16, wh16, wl16,
                                                   qkv_b, qkv, 3 * HID, HID);
    }
    // 2) RoPE + split to head-major bf16
    {
        int total = SEQ * NH * HD;
        rope_split_kernel<<<(total + 255) / 256, 256>>>(cosp, sinp);
    }
    // 3) Attention (bf16 3-term HMMA flash)
    {
        dim3 grid(SEQ / 128, NH);
        hmma_attn_kernel<<<grid, 256, ATTN_SMEM>>>(qh, ql, kh, kl, vh, vl,
                                                   cu, nseg, o16);
    }
    // 4) Output projection (fp16 2-term HMMA)
    {
        dim3 grid(HID / 128, SEQ / 128);
        hmma_gemm_kernel<<<grid, 256, HMMA_SMEM>>>(o16, ph16, pl16,
                                                   proj_b, out, HID, HID);
    }
}

// round 9
// speedup vs baseline: 1.2285x; 1.2285x over previous
#include <cuda_runtime.h>
#include <cuda_bf16.h>
#include <stdint.h>
#include <math.h>

#define SEQ 4096
#define HID 1280
#define NH 16
#define HD 80
#define HALF 40

// ---------------- scratch (device globals) ----------------------------------
__device__ float g_qkv[(size_t)SEQ * 3 * HID];

__device__ __nv_bfloat16 g_hh[(size_t)SEQ * HID];
__device__ __nv_bfloat16 g_hl[(size_t)SEQ * HID];
__device__ __nv_bfloat16 g_wh[(size_t)3 * HID * HID];
__device__ __nv_bfloat16 g_wl[(size_t)3 * HID * HID];
__device__ __nv_bfloat16 g_ph[(size_t)HID * HID];
__device__ __nv_bfloat16 g_pl[(size_t)HID * HID];

// split Q/K/V, head-major [h][s][d]; Q pre-scaled by HD^-0.5
__device__ __nv_bfloat16 g_qh[(size_t)NH * SEQ * HD];
__device__ __nv_bfloat16 g_ql[(size_t)NH * SEQ * HD];
__device__ __nv_bfloat16 g_kh[(size_t)NH * SEQ * HD];
__device__ __nv_bfloat16 g_kl[(size_t)NH * SEQ * HD];
__device__ __nv_bfloat16 g_vh[(size_t)NH * SEQ * HD];
__device__ __nv_bfloat16 g_vl[(size_t)NH * SEQ * HD];

// attention output, split bf16, seq-major [s][HID]
__device__ __nv_bfloat16 g_ah[(size_t)SEQ * HID];
__device__ __nv_bfloat16 g_al[(size_t)SEQ * HID];

// ---------------- PTX helpers ----------------------------------------------
__device__ __forceinline__ uint32_t smem_u32(const void* p) {
    uint32_t a;
    asm("{ .reg .u64 t; cvta.to.shared.u64 t, %1; cvt.u32.u64 %0, t; }"
        : "=r"(a) : "l"(p));
    return a;
}

__device__ __forceinline__ void ldsm4(uint32_t* r, uint32_t addr) {
    asm volatile("ldmatrix.sync.aligned.m8n8.x4.shared.b16 {%0,%1,%2,%3}, [%4];\n"
        : "=r"(r[0]), "=r"(r[1]), "=r"(r[2]), "=r"(r[3]) : "r"(addr));
}

__device__ __forceinline__ void ldsm4t(uint32_t* r, uint32_t addr) {
    asm volatile("ldmatrix.sync.aligned.m8n8.x4.trans.shared.b16 {%0,%1,%2,%3}, [%4];\n"
        : "=r"(r[0]), "=r"(r[1]), "=r"(r[2]), "=r"(r[3]) : "r"(addr));
}

__device__ __forceinline__ void mma16816(float* d, const uint32_t* a,
                                         const uint32_t* b) {
    asm volatile(
        "mma.sync.aligned.m16n8k16.row.col.f32.bf16.bf16.f32 "
        "{%0,%1,%2,%3}, {%4,%5,%6,%7}, {%8,%9}, {%0,%1,%2,%3};\n"
        : "+f"(d[0]), "+f"(d[1]), "+f"(d[2]), "+f"(d[3])
        : "r"(a[0]), "r"(a[1]), "r"(a[2]), "r"(a[3]), "r"(b[0]), "r"(b[1]));
}

__device__ __forceinline__ void cp16(uint32_t s, const void* g) {
    asm volatile("cp.async.cg.shared.global [%0], [%1], 16;\n" :: "r"(s), "l"(g));
}

__device__ __forceinline__ void splitpack(float x0, float x1,
                                          uint32_t& ph, uint32_t& pl) {
    __nv_bfloat162 h = __floats2bfloat162_rn(x0, x1);
    float h0 = __bfloat162float(h.x), h1 = __bfloat162float(h.y);
    __nv_bfloat162 l = __floats2bfloat162_rn(x0 - h0, x1 - h1);
    ph = *(uint32_t*)&h;
    pl = *(uint32_t*)&l;
}

// ---------------- fp32 -> (hi, lo) bf16 split -------------------------------
__global__ __launch_bounds__(256) void split_kernel(
    const float* __restrict__ src, __nv_bfloat16* __restrict__ hi,
    __nv_bfloat16* __restrict__ lo, int n)
{
    int i = blockIdx.x * blockDim.x + threadIdx.x;
    if (i >= n) return;
    float x = src[i];
    __nv_bfloat16 h = __float2bfloat16(x);
    hi[i] = h;
    lo[i] = __float2bfloat16(x - __bfloat162float(h));
}

// ---------------- HMMA split-bf16 GEMM (r5 config + term-outer MMA order) ---
#define BK 64
#define ASTR 72
#define TILE_B (128 * ASTR * 2)
#define STAGE_B (4 * TILE_B)
#define HMMA_SMEM (2 * STAGE_B)

__device__ __forceinline__ void gemm_prefetch(
    uint32_t sstage,
    const __nv_bfloat16* __restrict__ Agh, const __nv_bfloat16* __restrict__ Agl,
    const __nv_bfloat16* __restrict__ Bgh, const __nv_bfloat16* __restrict__ Bgl,
    int k0, int K, int tid)
{
    #pragma unroll
    for (int it = 0; it < 4; it++) {
        int idx = tid + it * 256;
        int r = idx >> 3, c8 = (idx & 7) << 3;
        uint32_t soff = (uint32_t)(r * ASTR + c8) * 2;
        size_t ga = (size_t)r * K + k0 + c8;
        cp16(sstage + soff,               Agh + ga);
        cp16(sstage + TILE_B + soff,      Agl + ga);
        cp16(sstage + 2 * TILE_B + soff,  Bgh + ga);
        cp16(sstage + 3 * TILE_B + soff,  Bgl + ga);
    }
}

__global__ __launch_bounds__(256, 1) void hmma_gemm_kernel(
    const __nv_bfloat16* __restrict__ Ah, const __nv_bfloat16* __restrict__ Al,
    const __nv_bfloat16* __restrict__ Bh, const __nv_bfloat16* __restrict__ Bl,
    const float* __restrict__ bias, float* __restrict__ C, int N, int K)
{
    extern __shared__ char smraw[];
    const uint32_t sb = smem_u32(smraw);
    const int tid = threadIdx.x;
    const int wid = tid >> 5, lane = tid & 31;
    const int wm = (wid >> 2) * 64;
    const int wn = (wid & 3) * 32;
    const int bm = blockIdx.y * 128, bn = blockIdx.x * 128;

    const int lg = lane >> 3, lr = lane & 7;
    const int a_r = lr + ((lg & 1) << 3), a_c = (lg >> 1) << 3;
    const int b_r = lr + ((lg >> 1) << 3), b_c = (lg & 1) << 3;

    const __nv_bfloat16* Agh = Ah + (size_t)bm * K;
    const __nv_bfloat16* Agl = Al + (size_t)bm * K;
    const __nv_bfloat16* Bgh = Bh + (size_t)bn * K;
    const __nv_bfloat16* Bgl = Bl + (size_t)bn * K;

    float acc[4][4][4];
    #pragma unroll
    for (int i = 0; i < 4; i++)
        #pragma unroll
        for (int j = 0; j < 4; j++)
            #pragma unroll
            for (int t = 0; t < 4; t++) acc[i][j][t] = 0.f;

    const int nc = K / BK;
    gemm_prefetch(sb, Agh, Agl, Bgh, Bgl, 0, K, tid);
    asm volatile("cp.async.commit_group;\n" ::: "memory");

    for (int c = 0; c < nc; c++) {
        if (c + 1 < nc) {
            gemm_prefetch(sb + ((c + 1) & 1) * STAGE_B, Agh, Agl, Bgh, Bgl,
                          (c + 1) * BK, K, tid);
            asm volatile("cp.async.commit_group;\n" ::: "memory");
            asm volatile("cp.async.wait_group 1;\n" ::: "memory");
        } else {
            asm volatile("cp.async.wait_group 0;\n" ::: "memory");
        }
        __syncthreads();

        const uint32_t s0 = sb + (c & 1) * STAGE_B;
        const uint32_t aH = s0, aL = s0 + TILE_B;
        const uint32_t bH = s0 + 2 * TILE_B, bL = s0 + 3 * TILE_B;

        #pragma unroll
        for (int ks = 0; ks < 4; ks++) {
            const int k = ks * 16;
            uint32_t ahf[4][4], alf[4][4], bhf[2][4], blf[2][4];
            #pragma unroll
            for (int i = 0; i < 4; i++) {
                uint32_t off = (uint32_t)((wm + i * 16 + a_r) * ASTR + k + a_c) * 2;
                ldsm4(ahf[i], aH + off);
                ldsm4(alf[i], aL + off);
            }
            #pragma unroll
            for (int p = 0; p < 2; p++) {
                uint32_t off = (uint32_t)((wn + p * 16 + b_r) * ASTR + k + b_c) * 2;
                ldsm4(bhf[p], bH + off);
                ldsm4(blf[p], bL + off);
            }
            // term-outer ordering: same-accumulator reuse distance = 16 MMAs
            #pragma unroll
            for (int t = 0; t < 3; t++)
                #pragma unroll
                for (int i = 0; i < 4; i++)
                    #pragma unroll
                    for (int j = 0; j < 4; j++) {
                        const uint32_t* bp = (t == 1)
                            ? &blf[j >> 1][(j & 1) * 2]
                            : &bhf[j >> 1][(j & 1) * 2];
                        const uint32_t* ap = (t == 2) ? alf[i] : ahf[i];
                        mma16816(acc[i][j], ap, bp);
                    }
        }
        __syncthreads();
    }

    #pragma unroll
    for (int i = 0; i < 4; i++) {
        int r0 = bm + wm + i * 16 + (lane >> 2);
        #pragma unroll
        for (int j = 0; j < 4; j++) {
            int c0 = bn + wn + j * 8 + ((lane & 3) << 1);
            float b0 = __ldg(bias + c0), b1 = __ldg(bias + c0 + 1);
            *(float2*)(C + (size_t)r0 * N + c0) =
                make_float2(acc[i][j][0] + b0, acc[i][j][1] + b1);
            *(float2*)(C + (size_t)(r0 + 8) * N + c0) =
                make_float2(acc[i][j][2] + b0, acc[i][j][3] + b1);
        }
    }
}

// ---------------- RoPE + split to bf16 hi/lo, head-major --------------------
__global__ __launch_bounds__(256) void rope_split_kernel(
    const float* __restrict__ cosp, const float* __restrict__ sinp)
{
    int idx = blockIdx.x * blockDim.x + threadIdx.x;
    if (idx >= SEQ * NH * HD) return;
    int d = idx % HD;
    int h = (idx / HD) % NH;
    int s = idx / (HD * NH);
    float c = cosp[s * HD + d], sn = sinp[s * HD + d];
    const float* base = g_qkv + (size_t)s * 3 * HID + h * HD;
    float qv = base[d];
    float kv = base[HID + d];
    float vv = base[2 * HID + d];
    float qr = (d < HALF) ? -base[d + HALF] : base[d - HALF];
    float kr = (d < HALF) ? -base[HID + d + HALF] : base[HID + d - HALF];
    const float scale = rsqrtf((float)HD);
    float q = (qv * c + qr * sn) * scale;
    float k = kv * c + kr * sn;
    size_t o = (size_t)h * SEQ * HD + (size_t)s * HD + d;
    __nv_bfloat16 qh = __float2bfloat16(q);
    __nv_bfloat16 kh = __float2bfloat16(k);
    __nv_bfloat16 vh = __float2bfloat16(vv);
    g_qh[o] = qh; g_ql[o] = __float2bfloat16(q - __bfloat162float(qh));
    g_kh[o] = kh; g_kl[o] = __float2bfloat16(k - __bfloat162float(kh));
    g_vh[o] = vh; g_vl[o] = __float2bfloat16(vv - __bfloat162float(vh));
}

// ---------------- HMMA flash attention: split-bf16, KV double-buffered ------
#define QSTR 88
#define ATILE (128 * QSTR * 2)          // 22528 bytes per tile
#define ATTN_SMEM (10 * ATILE)          // Qh Ql + 2 stages x (Kh Kl Vh Vl)

__device__ __forceinline__ void kv_prefetch(
    uint32_t stage_base,
    const __nv_bfloat16* __restrict__ Kgh, const __nv_bfloat16* __restrict__ Kgl,
    const __nv_bfloat16* __restrict__ Vgh, const __nv_bfloat16* __restrict__ Vgl,
    int kb, int tid)
{
    for (int idx = tid; idx < 128 * 10; idx += 256) {
        int row = idx / 10, c8 = (idx % 10) * 8;
        uint32_t soff = (uint32_t)(row * QSTR + c8) * 2;
        size_t ga = (size_t)(kb + row) * HD + c8;
        cp16(stage_base + soff,             Kgh + ga);
        cp16(stage_base + ATILE + soff,     Kgl + ga);
        cp16(stage_base + 2 * ATILE + soff, Vgh + ga);
        cp16(stage_base + 3 * ATILE + soff, Vgl + ga);
    }
}

__global__ __launch_bounds__(256, 1) void hmma_attn_kernel(
    const __nv_bfloat16* __restrict__ Qh_, const __nv_bfloat16* __restrict__ Ql_,
    const __nv_bfloat16* __restrict__ Kh_, const __nv_bfloat16* __restrict__ Kl_,
    const __nv_bfloat16* __restrict__ Vh_, const __nv_bfloat16* __restrict__ Vl_,
    const int* __restrict__ cu, int nseg,
    __nv_bfloat16* __restrict__ Oh_, __nv_bfloat16* __restrict__ Ol_)
{
    extern __shared__ char smraw[];
    const uint32_t sb = smem_u32(smraw);
    const uint32_t sQh = sb, sQl = sb + ATILE;
    __shared__ int cus[17];

    const int tid = threadIdx.x;
    const int wid = tid >> 5, lane = tid & 31;
    const int h = blockIdx.y;
    const int r0 = blockIdx.x * 128;

    const int lg = lane >> 3, lr = lane & 7;
    const int a_r = lr + ((lg & 1) << 3), a_c = (lg >> 1) << 3;
    const int b_r = lr + ((lg >> 1) << 3), b_c = (lg & 1) << 3;

    if (tid <= nseg) cus[tid] = cu[tid];

    // Q tile prefetch (group 0)
    {
        const __nv_bfloat16* qh = Qh_ + ((size_t)h * SEQ + r0) * HD;
        const __nv_bfloat16* ql = Ql_ + ((size_t)h * SEQ + r0) * HD;
        for (int idx = tid; idx < 128 * 10; idx += 256) {
            int row = idx / 10, c8 = (idx % 10) * 8;
            uint32_t soff = (uint32_t)(row * QSTR + c8) * 2;
            cp16(sQh + soff, qh + (size_t)row * HD + c8);
            cp16(sQl + soff, ql + (size_t)row * HD + c8);
        }
        asm volatile("cp.async.commit_group;\n" ::: "memory");
    }
    __syncthreads();   // cus visible

    const int gr1 = r0 + 16 * wid + (lane >> 2);
    int st1 = 0, en1 = SEQ, st2 = 0, en2 = SEQ;
    for (int t = 0; t < nseg; t++) {
        if (gr1     >= cus[t]) { st1 = cus[t]; en1 = cus[t + 1]; }
        if (gr1 + 8 >= cus[t]) { st2 = cus[t]; en2 = cus[t + 1]; }
    }
    int blk_start = 0, blk_end = SEQ;
    for (int t = 0; t < nseg; t++) {
        if (r0 >= cus[t]) blk_start = cus[t];
        if (r0 + 127 >= cus[t]) blk_end = cus[t + 1];
    }
    const int kb0 = (blk_start / 128) * 128;

    const __nv_bfloat16* Kgh = Kh_ + (size_t)h * SEQ * HD;
    const __nv_bfloat16* Kgl = Kl_ + (size_t)h * SEQ * HD;
    const __nv_bfloat16* Vgh = Vh_ + (size_t)h * SEQ * HD;
    const __nv_bfloat16* Vgl = Vl_ + (size_t)h * SEQ * HD;

    // first KV tile into stage 0 (group 1)
    kv_prefetch(sb + 2 * ATILE, Kgh, Kgl, Vgh, Vgl, kb0, tid);
    asm volatile("cp.async.commit_group;\n" ::: "memory");

    float m1 = -INFINITY, m2 = -INFINITY, l1 = 0.f, l2 = 0.f;
    float oacc[10][4];
    #pragma unroll
    for (int j = 0; j < 10; j++)
        #pragma unroll
        for (int t = 0; t < 4; t++) oacc[j][t] = 0.f;

    int buf = 0;
    for (int kb = kb0; kb < blk_end; kb += 128) {
        if (kb + 128 < blk_end) {
            kv_prefetch(sb + (2 + 4 * (buf ^ 1)) * ATILE,
                        Kgh, Kgl, Vgh, Vgl, kb + 128, tid);
            asm volatile("cp.async.commit_group;\n" ::: "memory");
            asm volatile("cp.async.wait_group 1;\n" ::: "memory");
        } else {
            asm volatile("cp.async.wait_group 0;\n" ::: "memory");
        }
        __syncthreads();

        const uint32_t cKh = sb + (2 + 4 * buf) * ATILE;
        const uint32_t cKl = cKh + ATILE;
        const uint32_t cVh = cKh + 2 * ATILE;
        const uint32_t cVl = cKh + 3 * ATILE;

        // ---- S = Q K^T ----
        float sc[16][4];
        #pragma unroll
        for (int j = 0; j < 16; j++)
            #pragma unroll
            for (int t = 0; t < 4; t++) sc[j][t] = 0.f;

        #pragma unroll
        for (int kc = 0; kc < 5; kc++) {
            uint32_t ah[4], al[4];
            uint32_t qoff = (uint32_t)((16 * wid + a_r) * QSTR + kc * 16 + a_c) * 2;
            ldsm4(ah, sQh + qoff);
            ldsm4(al, sQl + qoff);
            #pragma unroll
            for (int ng = 0; ng < 8; ng++) {
                uint32_t bh[4], bl[4];
                uint32_t koff = (uint32_t)((ng * 16 + b_r) * QSTR + kc * 16 + b_c) * 2;
                ldsm4(bh, cKh + koff);
                ldsm4(bl, cKl + koff);
                // alternate accumulators between same-acc reuses
                mma16816(sc[2 * ng],     ah, bh);
                mma16816(sc[2 * ng + 1], ah, bh + 2);
                mma16816(sc[2 * ng],     ah, bl);
                mma16816(sc[2 * ng + 1], ah, bl + 2);
                mma16816(sc[2 * ng],     al, bh);
                mma16816(sc[2 * ng + 1], al, bh + 2);
            }
        }

        // ---- mask + online softmax ----
        float tm1 = -INFINITY, tm2 = -INFINITY;
        #pragma unroll
        for (int j = 0; j < 16; j++) {
            int c0 = kb + j * 8 + ((lane & 3) << 1);
            int c1 = c0 + 1;
            if (c0 < st1 || c0 >= en1) sc[j][0] = -INFINITY;
            if (c1 < st1 || c1 >= en1) sc[j][1] = -INFINITY;
            if (c0 < st2 || c0 >= en2) sc[j][2] = -INFINITY;
            if (c1 < st2 || c1 >= en2) sc[j][3] = -INFINITY;
            tm1 = fmaxf(tm1, fmaxf(sc[j][0], sc[j][1]));
            tm2 = fmaxf(tm2, fmaxf(sc[j][2], sc[j][3]));
        }
        tm1 = fmaxf(tm1, __shfl_xor_sync(0xffffffffu, tm1, 1, 4));
        tm1 = fmaxf(tm1, __shfl_xor_sync(0xffffffffu, tm1, 2, 4));
        tm2 = fmaxf(tm2, __shfl_xor_sync(0xffffffffu, tm2, 1, 4));
        tm2 = fmaxf(tm2, __shfl_xor_sync(0xffffffffu, tm2, 2, 4));

        float mn1 = fmaxf(m1, tm1), mn2 = fmaxf(m2, tm2);
        bool dead1 = (mn1 == -INFINITY), dead2 = (mn2 == -INFINITY);
        float f1 = dead1 ? 1.f : __expf(m1 - mn1);
        float f2 = dead2 ? 1.f : __expf(m2 - mn2);
        m1 = mn1; m2 = mn2;

        float rs1 = 0.f, rs2 = 0.f;
        #pragma unroll
        for (int j = 0; j < 16; j++) {
            float p0 = dead1 ? 0.f : __expf(sc[j][0] - mn1);
            float p1 = dead1 ? 0.f : __expf(sc[j][1] - mn1);
            float p2 = dead2 ? 0.f : __expf(sc[j][2] - mn2);
            float p3 = dead2 ? 0.f : __expf(sc[j][3] - mn2);
            sc[j][0] = p0; sc[j][1] = p1; sc[j][2] = p2; sc[j][3] = p3;
            rs1 += p0 + p1; rs2 += p2 + p3;
        }
        rs1 += __shfl_xor_sync(0xffffffffu, rs1, 1, 4);
        rs1 += __shfl_xor_sync(0xffffffffu, rs1, 2, 4);
        rs2 += __shfl_xor_sync(0xffffffffu, rs2, 1, 4);
        rs2 += __shfl_xor_sync(0xffffffffu, rs2, 2, 4);
        l1 = l1 * f1 + rs1;
        l2 = l2 * f2 + rs2;

        #pragma unroll
        for (int j = 0; j < 10; j++) {
            oacc[j][0] *= f1; oacc[j][1] *= f1;
            oacc[j][2] *= f2; oacc[j][3] *= f2;
        }

        // ---- O += P V ----
        #pragma unroll
        for (int kc = 0; kc < 8; kc++) {
            uint32_t pah[4], pal[4];
            splitpack(sc[2 * kc][0],     sc[2 * kc][1],     pah[0], pal[0]);
            splitpack(sc[2 * kc][2],     sc[2 * kc][3],     pah[1], pal[1]);
            splitpack(sc[2 * kc + 1][0], sc[2 * kc + 1][1], pah[2], pal[2]);
            splitpack(sc[2 * kc + 1][2], sc[2 * kc + 1][3], pah[3], pal[3]);
            #pragma unroll
            for (int dv = 0; dv < 5; dv++) {
                uint32_t vh[4], vl[4];
                uint32_t voff = (uint32_t)((kc * 16 + (lane & 15)) * QSTR
                                 + dv * 16 + ((lane >> 4) << 3)) * 2;
                ldsm4t(vh, cVh + voff);
                ldsm4t(vl, cVl + voff);
                mma16816(oacc[2 * dv],     pah, vh);
                mma16816(oacc[2 * dv + 1], pah, vh + 2);
                mma16816(oacc[2 * dv],     pah, vl);
                mma16816(oacc[2 * dv + 1], pah, vl + 2);
                mma16816(oacc[2 * dv],     pal, vh);
                mma16816(oacc[2 * dv + 1], pal, vh + 2);
            }
        }
        __syncthreads();   // protect stage before it is overwritten next iter
        buf ^= 1;
    }

    float inv1 = (l1 > 0.f) ? 1.f / l1 : 0.f;
    float inv2 = (l2 > 0.f) ? 1.f / l2 : 0.f;
    #pragma unroll
    for (int j = 0; j < 10; j++) {
        int dcol = h * HD + j * 8 + ((lane & 3) << 1);
        size_t o1 = (size_t)gr1 * HID + dcol;
        size_t o2 = (size_t)(gr1 + 8) * HID + dcol;
        uint32_t ph, pl;
        splitpack(oacc[j][0] * inv1, oacc[j][1] * inv1, ph, pl);
        *(uint32_t*)(Oh_ + o1) = ph;
        *(uint32_t*)(Ol_ + o1) = pl;
        splitpack(oacc[j][2] * inv2, oacc[j][3] * inv2, ph, pl);
        *(uint32_t*)(Oh_ + o2) = ph;
        *(uint32_t*)(Ol_ + o2) = pl;
    }
}

// ---------------- launch ----------------------------------------------------
extern "C" void kernel_launch(void* const* d_in, const int* in_sizes, int n_in,
                              void* d_out, int out_size)
{
    const float* hidden = (const float*)d_in[0];
    const float* cosp   = (const float*)d_in[1];
    const float* sinp   = (const float*)d_in[2];
    const float* qkv_w  = (const float*)d_in[3];
    const float* qkv_b  = (const float*)d_in[4];
    const float* proj_w = (const float*)d_in[5];
    const float* proj_b = (const float*)d_in[6];
    const int*   cu     = (const int*)d_in[7];
    const int    nseg   = in_sizes[7] - 1;
    float* out = (float*)d_out;

    float* qkv;
    cudaGetSymbolAddress((void**)&qkv, g_qkv);
    __nv_bfloat16 *hh, *hl, *wh, *wl, *ph, *pl;
    __nv_bfloat16 *qh, *ql, *kh, *kl, *vh, *vl, *ah, *al;
    cudaGetSymbolAddress((void**)&hh, g_hh);
    cudaGetSymbolAddress((void**)&hl, g_hl);
    cudaGetSymbolAddress((void**)&wh, g_wh);
    cudaGetSymbolAddress((void**)&wl, g_wl);
    cudaGetSymbolAddress((void**)&ph, g_ph);
    cudaGetSymbolAddress((void**)&pl, g_pl);
    cudaGetSymbolAddress((void**)&qh, g_qh);
    cudaGetSymbolAddress((void**)&ql, g_ql);
    cudaGetSymbolAddress((void**)&kh, g_kh);
    cudaGetSymbolAddress((void**)&kl, g_kl);
    cudaGetSymbolAddress((void**)&vh, g_vh);
    cudaGetSymbolAddress((void**)&vl, g_vl);
    cudaGetSymbolAddress((void**)&ah, g_ah);
    cudaGetSymbolAddress((void**)&al, g_al);

    cudaFuncSetAttribute(hmma_gemm_kernel,
                         cudaFuncAttributeMaxDynamicSharedMemorySize, HMMA_SMEM);
    cudaFuncSetAttribute(hmma_attn_kernel,
                         cudaFuncAttributeMaxDynamicSharedMemorySize, ATTN_SMEM);

    // 0) split inputs/weights
    {
        int n1 = SEQ * HID;
        split_kernel<<<(n1 + 255) / 256, 256>>>(hidden, hh, hl, n1);
        int n2 = 3 * HID * HID;
        split_kernel<<<(n2 + 255) / 256, 256>>>(qkv_w, wh, wl, n2);
        int n3 = HID * HID;
        split_kernel<<<(n3 + 255) / 256, 256>>>(proj_w, ph, pl, n3);
    }
    // 1) QKV GEMM (bf16 3-term HMMA)
    {
        dim3 grid((3 * HID) / 128, SEQ / 128);
        hmma_gemm_kernel<<<grid, 256, HMMA_SMEM>>>(hh, hl, wh, wl,
                                                   qkv_b, qkv, 3 * HID, HID);
    }
    // 2) RoPE + split to head-major bf16
    {
        int total = SEQ * NH * HD;
        rope_split_kernel<<<(total + 255) / 256, 256>>>(cosp, sinp);
    }
    // 3) Attention (bf16 3-term HMMA flash, KV double-buffered)
    {
        dim3 grid(SEQ / 128, NH);
        hmma_attn_kernel<<<grid, 256, ATTN_SMEM>>>(qh, ql, kh, kl, vh, vl,
                                                   cu, nseg, ah, al);
    }
    // 4) Output projection (bf16 3-term HMMA)
    {
        dim3 grid(HID / 128, SEQ / 128);
        hmma_gemm_kernel<<<grid, 256, HMMA_SMEM>>>(ah, al, ph, pl,
                                                   proj_b, out, HID, HID);
    }
}